// round 10
// baseline (speedup 1.0000x reference)
#include <cuda_runtime.h>
#include <math.h>
#include <float.h>

#define NN    8192
#define DIM   512
#define TOPK  10
#define SCALE 0.04419417382415922f   // 512^-0.5 rounded to fp32

typedef unsigned long long ull;

// 32 MB fp32 scratch for the two embeddings (static device alloc: allowed)
__device__ float g_e[2][NN * DIM];

// packed fp32x2 FMA (SASS FFMA2) — bit-exact IEEE fp32 per lane
#define FMA2(d, a, b) asm("fma.rn.f32x2 %0, %1, %2, %0;" : "+l"(d) : "l"(a), "l"(b))
#define PACKF2(d, x, y) asm("mov.b64 %0, {%1, %2};" : "=l"(d) : "f"(x), "f"(y))
#define UNPACKADD(f, p) do { float _lo, _hi; \
    asm("mov.b64 {%0, %1}, %2;" : "=f"(_lo), "=f"(_hi) : "l"(p)); \
    f = _lo + _hi; } while (0)

// ---------------------------------------------------------------------------
// Kernel 1: E_z = X @ W_z^T + b_z   (z=0: Wh/bh, z=1: Wt/bt)  (unchanged)
// ---------------------------------------------------------------------------
__global__ __launch_bounds__(256) void embed_gemm(
    const float* __restrict__ X,
    const float* __restrict__ Wh, const float* __restrict__ bh,
    const float* __restrict__ Wt, const float* __restrict__ bt)
{
    const float* __restrict__ W  = blockIdx.z ? Wt : Wh;
    const float* __restrict__ bz = blockIdx.z ? bt : bh;
    float* E = g_e[blockIdx.z];

    __shared__ float As[16 * 132];
    __shared__ float Bs[16 * 68];

    const int tid = threadIdx.x;
    const int tx = tid & 15, ty = tid >> 4;
    const int brow = blockIdx.y * 128;
    const int bcol = blockIdx.x * 64;

    float acc[8][4];
    #pragma unroll
    for (int i = 0; i < 8; i++)
        #pragma unroll
        for (int j = 0; j < 4; j++) acc[i][j] = 0.f;

    for (int kt = 0; kt < DIM; kt += 16) {
        #pragma unroll
        for (int i = 0; i < 2; i++) {
            int lin = tid + i * 256;
            int r = lin >> 2, kq = (lin & 3) * 4;
            float4 v = *(const float4*)(X + (size_t)(brow + r) * DIM + kt + kq);
            As[(kq + 0) * 132 + r] = v.x; As[(kq + 1) * 132 + r] = v.y;
            As[(kq + 2) * 132 + r] = v.z; As[(kq + 3) * 132 + r] = v.w;
        }
        {
            int r = tid >> 2, kq = (tid & 3) * 4;
            float4 v = *(const float4*)(W + (size_t)(bcol + r) * DIM + kt + kq);
            Bs[(kq + 0) * 68 + r] = v.x; Bs[(kq + 1) * 68 + r] = v.y;
            Bs[(kq + 2) * 68 + r] = v.z; Bs[(kq + 3) * 68 + r] = v.w;
        }
        __syncthreads();
        #pragma unroll
        for (int kk = 0; kk < 16; kk++) {
            float4 a0 = *(float4*)(As + kk * 132 + 4 * ty);
            float4 a1 = *(float4*)(As + kk * 132 + 64 + 4 * ty);
            float4 b  = *(float4*)(Bs + kk * 68 + 4 * tx);
            float av[8] = {a0.x, a0.y, a0.z, a0.w, a1.x, a1.y, a1.z, a1.w};
            float bw[4] = {b.x, b.y, b.z, b.w};
            #pragma unroll
            for (int i = 0; i < 8; i++)
                #pragma unroll
                for (int j = 0; j < 4; j++)
                    acc[i][j] = fmaf(av[i], bw[j], acc[i][j]);
        }
        __syncthreads();
    }
    float4 bb = *(const float4*)(bz + bcol + 4 * tx);
    #pragma unroll
    for (int i = 0; i < 8; i++) {
        int row = brow + ((i < 4) ? (4 * ty + i) : (64 + 4 * ty + (i - 4)));
        float4 o;
        o.x = acc[i][0] + bb.x; o.y = acc[i][1] + bb.y;
        o.z = acc[i][2] + bb.z; o.w = acc[i][3] + bb.w;
        *(float4*)(E + (size_t)row * DIM + bcol + 4 * tx) = o;
    }
}

// ---------------------------------------------------------------------------
// Kernel 2: fused logits GEMM (k-paired FFMA2, no packs) + top-10 + softmax.
// 256 threads (8 warps). CTA = 64 rows x 8192 cols in 128-col tiles.
// Warp w: rows 8w..8w+7; lane: cols 4*lane..4*lane+3.
// A resident in smem as (k,k+1) ull pairs [k2][row]; B streamed per 32-k
// chunk as ull pairs [k2][col], double-buffered; acc = even/odd-k partials.
// ---------------------------------------------------------------------------
#define LDAP  66                        // ull stride of Ahp row (64 rows + pad)
#define LDBP  132                       // ull stride of Bsp row (128 cols + pad)
#define K2C   16                        // k2 pairs per chunk (32 k)
#define AHP_ULL   (256 * LDAP)          // 16896 ull = 135168 B
#define BUF_ULL   (K2C * LDBP)          // 2112 ull per buffer
#define LDL   132                       // float stride of Ls row
#define LS_FLOATS (64 * LDL)            // 8448 floats = 33792 B (= 2 B bufs)
#define SMEM_BYTES (AHP_ULL * 8 + LS_FLOATS * 4)   // 168960 B

__global__ __launch_bounds__(256) void logits_topk(float* __restrict__ out)
{
    extern __shared__ char smraw[];
    ull*   Ahp = (ull*)smraw;                     // [k2][row] A pairs
    float* Ls  = (float*)(smraw + AHP_ULL * 8);   // [64][132] logits / merge
    ull*   Bsp = (ull*)Ls;                        // [2][K2C][LDBP] aliases Ls

    const float* __restrict__ eh = g_e[0];
    const float* __restrict__ et = g_e[1];

    const int tid  = threadIdx.x;
    const int lane = tid & 31;
    const int rg   = tid >> 5;          // warp = row group: rows 8*rg..8*rg+7
    const int brow = blockIdx.x * 64;

    // ---- phase 0: load e_h [64][512] -> Ahp[k2][row] as (k,k+1) pairs ----
    #pragma unroll
    for (int i = 0; i < 32; i++) {
        int lin = tid + i * 256;
        int r = lin >> 7;
        int kq = (lin & 127) * 4;
        float4 v = *(const float4*)(eh + (size_t)(brow + r) * DIM + kq);
        ull p01, p23;
        PACKF2(p01, v.x, v.y);
        PACKF2(p23, v.z, v.w);
        Ahp[((kq >> 1) + 0) * LDAP + r] = p01;
        Ahp[((kq >> 1) + 1) * LDAP + r] = p23;
    }

    // per-thread partial top-10: row = tid>>2, interleaved 4-col chunks
    float tv[TOPK]; int ti[TOPK];
    #pragma unroll
    for (int s = 0; s < TOPK; s++) { tv[s] = -FLT_MAX; ti[s] = 0; }
    const int qr = tid >> 2;            // 0..63
    const int qq = tid & 3;             // phase 0..3

    // B loader: per chunk 128 cols x 32 k; thread t: col = t>>1,
    // k-quadrants kq0 = (t&1)*16 .. kq0+12 (4 float4)
    const int lcol = tid >> 1;
    const int lkq  = (tid & 1) * 16;

    __syncthreads();

    for (int ct = 0; ct < NN; ct += 128) {
        const float* etb = et + (size_t)(ct + lcol) * DIM;

        // prime chunk 0 into buf 0
        float4 pv[4];
        #pragma unroll
        for (int q = 0; q < 4; q++)
            pv[q] = *(const float4*)(etb + lkq + 4 * q);
        #pragma unroll
        for (int q = 0; q < 4; q++) {
            ull p01, p23;
            PACKF2(p01, pv[q].x, pv[q].y);
            PACKF2(p23, pv[q].z, pv[q].w);
            int k2 = (lkq >> 1) + 2 * q;
            Bsp[(k2 + 0) * LDBP + lcol] = p01;
            Bsp[(k2 + 1) * LDBP + lcol] = p23;
        }

        ull acc[8][4];
        #pragma unroll
        for (int i = 0; i < 8; i++)
            #pragma unroll
            for (int j = 0; j < 4; j++) acc[i][j] = 0ull;

        #pragma unroll 1
        for (int c = 0; c < 16; c++) {
            __syncthreads();
            if (c < 15) {
                #pragma unroll
                for (int q = 0; q < 4; q++)
                    pv[q] = *(const float4*)(etb + (c + 1) * 32 + lkq + 4 * q);
            }
            const ull* Bc = Bsp + (c & 1) * BUF_ULL;
            const ull* Ac = Ahp + c * K2C * LDAP;
            #pragma unroll
            for (int k2 = 0; k2 < K2C; k2++) {
                ulonglong2 a01 = *(const ulonglong2*)(Ac + k2 * LDAP + 8 * rg);
                ulonglong2 a23 = *(const ulonglong2*)(Ac + k2 * LDAP + 8 * rg + 2);
                ulonglong2 a45 = *(const ulonglong2*)(Ac + k2 * LDAP + 8 * rg + 4);
                ulonglong2 a67 = *(const ulonglong2*)(Ac + k2 * LDAP + 8 * rg + 6);
                ulonglong2 b01 = *(const ulonglong2*)(Bc + k2 * LDBP + 4 * lane);
                ulonglong2 b23 = *(const ulonglong2*)(Bc + k2 * LDBP + 4 * lane + 2);
                ull av[8] = {a01.x, a01.y, a23.x, a23.y, a45.x, a45.y, a67.x, a67.y};
                #pragma unroll
                for (int i = 0; i < 8; i++) {
                    FMA2(acc[i][0], av[i], b01.x);
                    FMA2(acc[i][1], av[i], b01.y);
                    FMA2(acc[i][2], av[i], b23.x);
                    FMA2(acc[i][3], av[i], b23.y);
                }
            }
            if (c < 15) {
                ull* Bn = Bsp + ((c & 1) ^ 1) * BUF_ULL;
                #pragma unroll
                for (int q = 0; q < 4; q++) {
                    ull p01, p23;
                    PACKF2(p01, pv[q].x, pv[q].y);
                    PACKF2(p23, pv[q].z, pv[q].w);
                    int k2 = (lkq >> 1) + 2 * q;
                    Bn[(k2 + 0) * LDBP + lcol] = p01;
                    Bn[(k2 + 1) * LDBP + lcol] = p23;
                }
            }
        }
        __syncthreads();   // all reads of Bsp done (Ls aliases it)

        // reduce even/odd partials and dump tile to Ls
        #pragma unroll
        for (int i = 0; i < 8; i++) {
            float4 o;
            UNPACKADD(o.x, acc[i][0]);
            UNPACKADD(o.y, acc[i][1]);
            UNPACKADD(o.z, acc[i][2]);
            UNPACKADD(o.w, acc[i][3]);
            *(float4*)(Ls + (8 * rg + i) * LDL + 4 * lane) = o;
        }
        __syncthreads();

        // scan: 4 threads/row, each reads 8 interleaved float4 chunks
        {
            const float* Lr = Ls + qr * LDL + qq * 4;
            #pragma unroll
            for (int b8 = 0; b8 < 8; b8++) {
                float4 v4 = *(const float4*)(Lr + 16 * b8);
                int cbase = ct + qq * 4 + 16 * b8;
                float vv[4] = {v4.x, v4.y, v4.z, v4.w};
                #pragma unroll
                for (int e = 0; e < 4; e++) {
                    float v = vv[e];
                    if (v > tv[TOPK - 1]) {
                        float cv = v; int ci = cbase + e;
                        #pragma unroll
                        for (int s = 0; s < TOPK; s++) {
                            if (cv > tv[s]) {
                                float tf = tv[s]; tv[s] = cv; cv = tf;
                                int tii = ti[s];  ti[s] = ci; ci = tii;
                            }
                        }
                    }
                }
            }
        }
        __syncthreads();   // scan done before next tile's prime STS
    }

    // ---- merge 4 partial lists per row, softmax, emit ----
    float* candv = Ls;                       // [64][40]
    int*   candi = (int*)(Ls + 64 * 40);     // [64][40]
    #pragma unroll
    for (int s = 0; s < TOPK; s++) {
        candv[qr * 40 + qq * TOPK + s] = tv[s];
        candi[qr * 40 + qq * TOPK + s] = ti[s];
    }
    __syncthreads();

    if (tid < 64) {
        int r = tid;
        float wv[TOPK]; int wi[TOPK];
        #pragma unroll
        for (int s = 0; s < TOPK; s++) {
            float bvv = -FLT_MAX; int bii = 0x7fffffff; int bc = 0;
            for (int c = 0; c < 40; c++) {
                float v = candv[r * 40 + c];
                int  ii = candi[r * 40 + c];
                if (v > bvv || (v == bvv && ii < bii)) { bvv = v; bii = ii; bc = c; }
            }
            candv[r * 40 + bc] = -FLT_MAX;
            wv[s] = bvv; wi[s] = bii;
        }
        float pw[TOPK], psum = 0.f;
        #pragma unroll
        for (int s = 0; s < TOPK; s++) {
            pw[s] = __expf((wv[s] - wv[0]) * SCALE);
            psum += pw[s];
        }
        float inv = 1.0f / psum;
        int row = brow + r;
        #pragma unroll
        for (int s = 0; s < TOPK; s++) {
            out[(size_t)row * TOPK + s]                         = (float)row;
            out[(size_t)NN * TOPK + (size_t)row * TOPK + s]     = (float)wi[s];
            out[(size_t)2 * NN * TOPK + (size_t)row * TOPK + s] = pw[s] * inv;
        }
    }
}

// ---------------------------------------------------------------------------
extern "C" void kernel_launch(void* const* d_in, const int* in_sizes, int n_in,
                              void* d_out, int out_size)
{
    const float* X  = (const float*)d_in[0];
    const float* Wh = (const float*)d_in[1];
    const float* bh = (const float*)d_in[2];
    const float* Wt = (const float*)d_in[3];
    const float* bt = (const float*)d_in[4];
    float* out = (float*)d_out;

    cudaFuncSetAttribute(logits_topk, cudaFuncAttributeMaxDynamicSharedMemorySize,
                         SMEM_BYTES);

    embed_gemm<<<dim3(DIM / 64, NN / 128, 2), 256>>>(X, Wh, bh, Wt, bt);
    logits_topk<<<NN / 64, 256, SMEM_BYTES>>>(out);
}

// round 15
// speedup vs baseline: 1.6053x; 1.6053x over previous
#include <cuda_runtime.h>
#include <math.h>
#include <float.h>
#include <stdint.h>

#define NN    8192
#define DIM   512
#define TOPK  10
#define NCAND 16
#define SCALE 0.04419417382415922f   // 512^-0.5 rounded to fp32

// ---- static device scratch (allowed) ----
__device__ float g_e[2][NN * DIM];           // fp32 embeddings
__device__ float g_l[(size_t)NN * NN];       // approx logits (256 MB)

// ============================ helpers ============================
__device__ __forceinline__ uint32_t smem_u32(const void* p) {
    uint32_t a;
    asm("{ .reg .u64 t; cvta.to.shared.u64 t, %1; cvt.u32.u64 %0, t; }"
        : "=r"(a) : "l"(p));
    return a;
}
__device__ __forceinline__ void cp16(uint32_t dst, const void* src) {
    asm volatile("cp.async.ca.shared.global [%0], [%1], 16;"
                 :: "r"(dst), "l"(src) : "memory");
}
__device__ __forceinline__ void cp_commit() {
    asm volatile("cp.async.commit_group;" ::: "memory");
}
template <int N> __device__ __forceinline__ void cp_wait() {
    asm volatile("cp.async.wait_group %0;" :: "n"(N) : "memory");
}
// m16n8k8 tf32 mma (legacy HMMA path — baseline PTX, works on plain sm_103)
__device__ __forceinline__ void mma_tf32(float* d, const uint32_t* a, const uint32_t* b) {
    asm volatile(
        "mma.sync.aligned.m16n8k8.row.col.f32.tf32.tf32.f32 "
        "{%0,%1,%2,%3}, {%4,%5,%6,%7}, {%8,%9}, {%0,%1,%2,%3};"
        : "+f"(d[0]), "+f"(d[1]), "+f"(d[2]), "+f"(d[3])
        : "r"(a[0]), "r"(a[1]), "r"(a[2]), "r"(a[3]), "r"(b[0]), "r"(b[1]));
}

// ---------------------------------------------------------------------------
// Kernel 1: E_z = X @ W_z^T + b_z  (unchanged, proven)
// ---------------------------------------------------------------------------
__global__ __launch_bounds__(256) void embed_gemm(
    const float* __restrict__ X,
    const float* __restrict__ Wh, const float* __restrict__ bh,
    const float* __restrict__ Wt, const float* __restrict__ bt)
{
    const float* __restrict__ W  = blockIdx.z ? Wt : Wh;
    const float* __restrict__ bz = blockIdx.z ? bt : bh;
    float* E = g_e[blockIdx.z];

    __shared__ float As[16 * 132];
    __shared__ float Bs[16 * 68];

    const int tid = threadIdx.x;
    const int tx = tid & 15, ty = tid >> 4;
    const int brow = blockIdx.y * 128;
    const int bcol = blockIdx.x * 64;

    float acc[8][4];
    #pragma unroll
    for (int i = 0; i < 8; i++)
        #pragma unroll
        for (int j = 0; j < 4; j++) acc[i][j] = 0.f;

    for (int kt = 0; kt < DIM; kt += 16) {
        #pragma unroll
        for (int i = 0; i < 2; i++) {
            int lin = tid + i * 256;
            int r = lin >> 2, kq = (lin & 3) * 4;
            float4 v = *(const float4*)(X + (size_t)(brow + r) * DIM + kt + kq);
            As[(kq + 0) * 132 + r] = v.x; As[(kq + 1) * 132 + r] = v.y;
            As[(kq + 2) * 132 + r] = v.z; As[(kq + 3) * 132 + r] = v.w;
        }
        {
            int r = tid >> 2, kq = (tid & 3) * 4;
            float4 v = *(const float4*)(W + (size_t)(bcol + r) * DIM + kt + kq);
            Bs[(kq + 0) * 68 + r] = v.x; Bs[(kq + 1) * 68 + r] = v.y;
            Bs[(kq + 2) * 68 + r] = v.z; Bs[(kq + 3) * 68 + r] = v.w;
        }
        __syncthreads();
        #pragma unroll
        for (int kk = 0; kk < 16; kk++) {
            float4 a0 = *(float4*)(As + kk * 132 + 4 * ty);
            float4 a1 = *(float4*)(As + kk * 132 + 64 + 4 * ty);
            float4 b  = *(float4*)(Bs + kk * 68 + 4 * tx);
            float av[8] = {a0.x, a0.y, a0.z, a0.w, a1.x, a1.y, a1.z, a1.w};
            float bw[4] = {b.x, b.y, b.z, b.w};
            #pragma unroll
            for (int i = 0; i < 8; i++)
                #pragma unroll
                for (int j = 0; j < 4; j++)
                    acc[i][j] = fmaf(av[i], bw[j], acc[i][j]);
        }
        __syncthreads();
    }
    float4 bb = *(const float4*)(bz + bcol + 4 * tx);
    #pragma unroll
    for (int i = 0; i < 8; i++) {
        int row = brow + ((i < 4) ? (4 * ty + i) : (64 + 4 * ty + (i - 4)));
        float4 o;
        o.x = acc[i][0] + bb.x; o.y = acc[i][1] + bb.y;
        o.z = acc[i][2] + bb.z; o.w = acc[i][3] + bb.w;
        *(float4*)(E + (size_t)row * DIM + bcol + 4 * tx) = o;
    }
}

// ---------------------------------------------------------------------------
// Kernel 2: approx logits GEMM via tf32 mma.sync -> g_l
// Grid (64, 64): CTA = 128x128 tile, K streamed in 32-chunks via cp.async.
// smem layout per buffer: A[128][36] fp32 | B[128][36] fp32 (pad -> no conflicts)
// Warp (8): warpM = (w&3)*32, warpN = (w>>2)*64; warp tile 32x64.
// ---------------------------------------------------------------------------
#define LDK     36
#define OP_U32  (128 * LDK)             // 4608 u32 per operand
#define BUF_U32 (2 * OP_U32)            // A+B per buffer
#define SMEM_MMA (2 * BUF_U32 * 4)      // 73728 bytes

__global__ __launch_bounds__(256, 2) void logits_mma()
{
    extern __shared__ uint32_t smu[];
    const int tid  = threadIdx.x;
    const int lane = tid & 31;
    const int wid  = tid >> 5;
    const int warpM = (wid & 3) * 32;
    const int warpN = (wid >> 2) * 64;
    const int mrow = blockIdx.y * 128;
    const int ncol = blockIdx.x * 128;

    // loader role: tid<128 -> A (e_h rows), else B (e_t rows); one row each
    const int lrow = tid & 127;
    const int isB  = tid >> 7;
    const float* src = isB ? g_e[1] + (size_t)(ncol + lrow) * DIM
                           : g_e[0] + (size_t)(mrow + lrow) * DIM;
    const uint32_t sdst0 = smem_u32(smu) + (isB * OP_U32 + lrow * LDK) * 4;

    // prime chunk 0 -> buf 0
    #pragma unroll
    for (int q = 0; q < 8; q++)
        cp16(sdst0 + q * 16, src + q * 4);
    cp_commit();

    float acc[2][8][4];
    #pragma unroll
    for (int mt = 0; mt < 2; mt++)
        #pragma unroll
        for (int nt = 0; nt < 8; nt++)
            #pragma unroll
            for (int j = 0; j < 4; j++) acc[mt][nt][j] = 0.f;

    #pragma unroll 1
    for (int c = 0; c < 16; c++) {
        if (c < 15) {
            uint32_t d = sdst0 + (((c + 1) & 1) * BUF_U32) * 4;
            const float* s = src + (c + 1) * 32;
            #pragma unroll
            for (int q = 0; q < 8; q++)
                cp16(d + q * 16, s + q * 4);
            cp_commit();
            cp_wait<1>();
        } else {
            cp_wait<0>();
        }
        __syncthreads();

        const uint32_t* Ab = smu + (c & 1) * BUF_U32;
        const uint32_t* Bb = Ab + OP_U32;
        #pragma unroll
        for (int k8 = 0; k8 < 4; k8++) {
            const uint32_t* ap = Ab + (warpM + (lane >> 2)) * LDK + k8 * 8 + (lane & 3);
            const uint32_t* bp = Bb + (warpN + (lane >> 2)) * LDK + k8 * 8 + (lane & 3);
            uint32_t afr[2][4], bfr[8][2];
            #pragma unroll
            for (int mt = 0; mt < 2; mt++) {
                afr[mt][0] = ap[(mt * 16 + 0) * LDK + 0];
                afr[mt][1] = ap[(mt * 16 + 8) * LDK + 0];
                afr[mt][2] = ap[(mt * 16 + 0) * LDK + 4];
                afr[mt][3] = ap[(mt * 16 + 8) * LDK + 4];
            }
            #pragma unroll
            for (int nt = 0; nt < 8; nt++) {
                bfr[nt][0] = bp[nt * 8 * LDK + 0];
                bfr[nt][1] = bp[nt * 8 * LDK + 4];
            }
            #pragma unroll
            for (int mt = 0; mt < 2; mt++)
                #pragma unroll
                for (int nt = 0; nt < 8; nt++)
                    mma_tf32(acc[mt][nt], afr[mt], bfr[nt]);
        }
        __syncthreads();
    }

    // epilogue: D fragment m16n8: c0,c1 row=lane>>2, col=(lane&3)*2; c2,c3 row+8
    #pragma unroll
    for (int mt = 0; mt < 2; mt++) {
        #pragma unroll
        for (int nt = 0; nt < 8; nt++) {
            int r  = mrow + warpM + mt * 16 + (lane >> 2);
            int cc = ncol + warpN + nt * 8 + (lane & 3) * 2;
            float2 lo = {acc[mt][nt][0], acc[mt][nt][1]};
            float2 hi = {acc[mt][nt][2], acc[mt][nt][3]};
            *(float2*)(g_l + (size_t)r * NN + cc) = lo;
            *(float2*)(g_l + (size_t)(r + 8) * NN + cc) = hi;
        }
    }
}

// ---------------------------------------------------------------------------
// Kernel 3: per-row approx top-16 -> exact fp32 rescore -> top-10 + softmax.
// 1 warp per row; 8 warps per block; grid 1024.
// ---------------------------------------------------------------------------
__global__ __launch_bounds__(256) void topk_rescore(float* __restrict__ out)
{
    const int lane = threadIdx.x & 31;
    const int row  = blockIdx.x * 8 + (threadIdx.x >> 5);
    const float* Lr = g_l + (size_t)row * NN;

    // per-lane partial top-16 (ascending column scan -> stable ties)
    float tv[NCAND]; int ti[NCAND];
    #pragma unroll
    for (int s = 0; s < NCAND; s++) { tv[s] = -FLT_MAX; ti[s] = 0x7fffffff; }

    for (int i = 0; i < NN / 128; i++) {
        float4 v4 = *(const float4*)(Lr + i * 128 + lane * 4);
        float vv[4] = {v4.x, v4.y, v4.z, v4.w};
        int cbase = i * 128 + lane * 4;
        #pragma unroll
        for (int e = 0; e < 4; e++) {
            float v = vv[e];
            if (v > tv[NCAND - 1]) {
                float cv = v; int ci = cbase + e;
                #pragma unroll
                for (int s = 0; s < NCAND; s++) {
                    if (cv > tv[s]) {
                        float tf = tv[s]; tv[s] = cv; cv = tf;
                        int tx = ti[s];  ti[s] = ci; ci = tx;
                    }
                }
            }
        }
    }

    // warp tournament: 16 rounds of argmax (value desc, idx asc)
    int ci16[NCAND];
    #pragma unroll
    for (int s = 0; s < NCAND; s++) {
        float bv = tv[0]; int bi = ti[0];
        #pragma unroll
        for (int o = 16; o; o >>= 1) {
            float ov = __shfl_xor_sync(0xffffffffu, bv, o);
            int   oi = __shfl_xor_sync(0xffffffffu, bi, o);
            if (ov > bv || (ov == bv && oi < bi)) { bv = ov; bi = oi; }
        }
        ci16[s] = bi;
        bool won = (tv[0] == bv) && (ti[0] == bi);
        if (won) {
            #pragma unroll
            for (int j = 0; j < NCAND - 1; j++) { tv[j] = tv[j + 1]; ti[j] = ti[j + 1]; }
            tv[NCAND - 1] = -FLT_MAX; ti[NCAND - 1] = 0x7fffffff;
        }
    }

    // exact fp32 rescore of the 16 candidates (e_h[row] . e_t[cand])
    const float* ar = g_e[0] + (size_t)row * DIM + lane * 16;
    float4 a0 = *(const float4*)(ar + 0);
    float4 a1 = *(const float4*)(ar + 4);
    float4 a2 = *(const float4*)(ar + 8);
    float4 a3 = *(const float4*)(ar + 12);
    float rv[NCAND];
    #pragma unroll
    for (int cnd = 0; cnd < NCAND; cnd++) {
        const float* br = g_e[1] + (size_t)ci16[cnd] * DIM + lane * 16;
        float4 b0 = *(const float4*)(br + 0);
        float4 b1 = *(const float4*)(br + 4);
        float4 b2 = *(const float4*)(br + 8);
        float4 b3 = *(const float4*)(br + 12);
        float p = a0.x * b0.x;
        p = fmaf(a0.y, b0.y, p); p = fmaf(a0.z, b0.z, p); p = fmaf(a0.w, b0.w, p);
        p = fmaf(a1.x, b1.x, p); p = fmaf(a1.y, b1.y, p); p = fmaf(a1.z, b1.z, p); p = fmaf(a1.w, b1.w, p);
        p = fmaf(a2.x, b2.x, p); p = fmaf(a2.y, b2.y, p); p = fmaf(a2.z, b2.z, p); p = fmaf(a2.w, b2.w, p);
        p = fmaf(a3.x, b3.x, p); p = fmaf(a3.y, b3.y, p); p = fmaf(a3.z, b3.z, p); p = fmaf(a3.w, b3.w, p);
        #pragma unroll
        for (int o = 16; o; o >>= 1) p += __shfl_xor_sync(0xffffffffu, p, o);
        rv[cnd] = p;   // identical on all lanes
    }

    // exact selection of top-10 (value desc, idx asc) — all lanes redundantly
    float wv[TOPK]; int wi[TOPK];
    unsigned mask = 0;
    #pragma unroll
    for (int s = 0; s < TOPK; s++) {
        float bv = -FLT_MAX; int bi = 0x7fffffff; int bc = 0;
        #pragma unroll
        for (int cnd = 0; cnd < NCAND; cnd++) {
            if (!((mask >> cnd) & 1)) {
                if (rv[cnd] > bv || (rv[cnd] == bv && ci16[cnd] < bi)) {
                    bv = rv[cnd]; bi = ci16[cnd]; bc = cnd;
                }
            }
        }
        mask |= 1u << bc;
        wv[s] = bv; wi[s] = bi;
    }

    if (lane == 0) {
        float pw[TOPK], psum = 0.f;
        #pragma unroll
        for (int s = 0; s < TOPK; s++) {
            pw[s] = __expf((wv[s] - wv[0]) * SCALE);
            psum += pw[s];
        }
        float inv = 1.0f / psum;
        #pragma unroll
        for (int s = 0; s < TOPK; s++) {
            out[(size_t)row * TOPK + s]                         = (float)row;
            out[(size_t)NN * TOPK + (size_t)row * TOPK + s]     = (float)wi[s];
            out[(size_t)2 * NN * TOPK + (size_t)row * TOPK + s] = pw[s] * inv;
        }
    }
}

// ---------------------------------------------------------------------------
extern "C" void kernel_launch(void* const* d_in, const int* in_sizes, int n_in,
                              void* d_out, int out_size)
{
    const float* X  = (const float*)d_in[0];
    const float* Wh = (const float*)d_in[1];
    const float* bh = (const float*)d_in[2];
    const float* Wt = (const float*)d_in[3];
    const float* bt = (const float*)d_in[4];
    float* out = (float*)d_out;

    cudaFuncSetAttribute(logits_mma, cudaFuncAttributeMaxDynamicSharedMemorySize,
                         SMEM_MMA);

    embed_gemm<<<dim3(DIM / 64, NN / 128, 2), 256>>>(X, Wh, bh, Wt, bt);
    logits_mma<<<dim3(NN / 128, NN / 128), 256, SMEM_MMA>>>();
    topk_rescore<<<NN / 8, 256>>>(out);
}